// round 8
// baseline (speedup 1.0000x reference)
#include <cuda_runtime.h>
#include <cuda_bf16.h>
#include <cstdint>
#include <math.h>

typedef unsigned int u32;

// Problem constants
#define BB 2
#define TT 2048
#define NN 2048
#define HID 1024
#define HH 16
#define DH 64
#define HALF 32
#define NHH 32
#define MTOT (BB*TT)

#define LAMBDA_INIT 0.7008206631f
#define EPSV 1e-5f
#define SCALE 0.17677669529663689f  // 1/sqrt(32)

// ---------------- scratch ----------------------------------------------------
__device__ float g_qb[MTOT * HID];
__device__ float g_kb[BB * NN * HID];
__device__ float g_vb[BB * NN * HID];
__device__ float g_ob[BB * NHH * TT * DH];
__device__ float g_xb[MTOT * HID];
__device__ float g_lambda;

// ---------------- helpers ----------------------------------------------------
__device__ __forceinline__ u32 f2tf(float f) {
    u32 u;
    asm("cvt.rna.tf32.f32 %0, %1;" : "=r"(u) : "f"(f));
    return u;
}

__device__ __forceinline__ void mma_tf32(float c[4],
                                         u32 a0, u32 a1, u32 a2, u32 a3,
                                         u32 b0, u32 b1) {
    asm volatile(
        "mma.sync.aligned.m16n8k8.row.col.f32.tf32.tf32.f32 "
        "{%0,%1,%2,%3},{%4,%5,%6,%7},{%8,%9},{%0,%1,%2,%3};\n"
        : "+f"(c[0]), "+f"(c[1]), "+f"(c[2]), "+f"(c[3])
        : "r"(a0), "r"(a1), "r"(a2), "r"(a3), "r"(b0), "r"(b1));
}

// Paired-K column permutation: mma fragment pairs (k=t, k=t+4) land adjacent.
// k in [0,16): col' = (k&8) + (k&3)*2 + ((k>>2)&1)
__device__ __forceinline__ int kperm(int k) {
    return (k & 8) + ((k & 3) << 1) + ((k >> 2) & 1);
}

// ---------------- lambda ------------------------------------------------------
__global__ void lambda_kernel(const float* __restrict__ lq1, const float* __restrict__ lq2,
                              const float* __restrict__ lk1, const float* __restrict__ lk2) {
    int lane = threadIdx.x;
    float a = lq1[lane] * lk1[lane];
    float b = lq2[lane] * lk2[lane];
    #pragma unroll
    for (int off = 16; off > 0; off >>= 1) {
        a += __shfl_xor_sync(0xffffffffu, a, off);
        b += __shfl_xor_sync(0xffffffffu, b, off);
    }
    if (lane == 0) g_lambda = expf(a) - expf(b) + LAMBDA_INIT;
}

// ---------------- GEMM (tensor core, tf32): C = A @ W^T ----------------------
// 128x128 tile, BK=16 double-buffered, 256 threads (8 warps: 4 M x 2 N, 32x64 each).
// Paired-K smem layout; fragment loads are LDS.64.
#define GPAD 20

__device__ __forceinline__ void gemm_tc_body(const float* __restrict__ A,
                                             const float* __restrict__ W,
                                             float* __restrict__ C,
                                             int M, int Nc, int K) {
    __shared__ u32 As[2][128][GPAD];
    __shared__ u32 Ws[2][128][GPAD];

    int tid = threadIdx.x;
    int warp = tid >> 5;
    int lane = tid & 31;
    int g = lane >> 2, t = lane & 3;
    int wy = warp >> 1;          // 0..3 (M)
    int wx = warp & 1;           // 0..1 (N)
    int m0 = blockIdx.y * 128;
    int n0 = blockIdx.x * 128;

    int lm = tid >> 2;           // row within 64-row chunk
    int lk = (tid & 3) * 4;      // k offset (0,4,8,12)
    // store columns for this thread's 4 values (consecutive k = lk..lk+3)
    int sc0 = kperm(lk + 0), sc1 = kperm(lk + 1), sc2 = kperm(lk + 2), sc3 = kperm(lk + 3);

    float acc[2][8][4];
    #pragma unroll
    for (int mt = 0; mt < 2; mt++)
        #pragma unroll
        for (int nt = 0; nt < 8; nt++)
            #pragma unroll
            for (int i = 0; i < 4; i++) acc[mt][nt][i] = 0.f;

    // initial tile load (k0 = 0)
    #pragma unroll
    for (int it = 0; it < 2; it++) {
        int m = lm + it * 64;
        float4 av = *(const float4*)&A[(size_t)(m0 + m) * K + lk];
        float4 wv = *(const float4*)&W[(size_t)(n0 + m) * K + lk];
        As[0][m][sc0] = f2tf(av.x); As[0][m][sc1] = f2tf(av.y);
        As[0][m][sc2] = f2tf(av.z); As[0][m][sc3] = f2tf(av.w);
        Ws[0][m][sc0] = f2tf(wv.x); Ws[0][m][sc1] = f2tf(wv.y);
        Ws[0][m][sc2] = f2tf(wv.z); Ws[0][m][sc3] = f2tf(wv.w);
    }
    __syncthreads();

    int nk = K / 16;
    for (int kt = 0; kt < nk; kt++) {
        int buf = kt & 1;
        float4 av[2], wv[2];
        if (kt + 1 < nk) {
            int k0 = (kt + 1) * 16;
            #pragma unroll
            for (int it = 0; it < 2; it++) {
                int m = lm + it * 64;
                av[it] = *(const float4*)&A[(size_t)(m0 + m) * K + k0 + lk];
                wv[it] = *(const float4*)&W[(size_t)(n0 + m) * K + k0 + lk];
            }
        }

        #pragma unroll
        for (int ks = 0; ks < 16; ks += 8) {
            // A fragments: LDS.64 pairs (k=t, k=t+4)
            uint2 alo[2], ahi[2];
            #pragma unroll
            for (int mt = 0; mt < 2; mt++) {
                int mr = wy * 32 + mt * 16;
                alo[mt] = *(const uint2*)&As[buf][mr + g][ks + 2 * t];
                ahi[mt] = *(const uint2*)&As[buf][mr + g + 8][ks + 2 * t];
            }
            uint2 bfr[8];
            #pragma unroll
            for (int nt = 0; nt < 8; nt++) {
                int nr = wx * 64 + nt * 8 + g;
                bfr[nt] = *(const uint2*)&Ws[buf][nr][ks + 2 * t];
            }
            #pragma unroll
            for (int mt = 0; mt < 2; mt++)
                #pragma unroll
                for (int nt = 0; nt < 8; nt++)
                    mma_tf32(acc[mt][nt], alo[mt].x, ahi[mt].x, alo[mt].y, ahi[mt].y,
                             bfr[nt].x, bfr[nt].y);
        }

        if (kt + 1 < nk) {
            int nb = buf ^ 1;
            #pragma unroll
            for (int it = 0; it < 2; it++) {
                int m = lm + it * 64;
                As[nb][m][sc0] = f2tf(av[it].x); As[nb][m][sc1] = f2tf(av[it].y);
                As[nb][m][sc2] = f2tf(av[it].z); As[nb][m][sc3] = f2tf(av[it].w);
                Ws[nb][m][sc0] = f2tf(wv[it].x); Ws[nb][m][sc1] = f2tf(wv[it].y);
                Ws[nb][m][sc2] = f2tf(wv[it].z); Ws[nb][m][sc3] = f2tf(wv[it].w);
            }
        }
        __syncthreads();
    }

    // epilogue
    #pragma unroll
    for (int mt = 0; mt < 2; mt++) {
        #pragma unroll
        for (int nt = 0; nt < 8; nt++) {
            int row = m0 + wy * 32 + mt * 16 + g;
            int col = n0 + wx * 64 + nt * 8 + 2 * t;
            *(float2*)&C[(size_t)row * Nc + col] = make_float2(acc[mt][nt][0], acc[mt][nt][1]);
            *(float2*)&C[(size_t)(row + 8) * Nc + col] = make_float2(acc[mt][nt][2], acc[mt][nt][3]);
        }
    }
}

// single GEMM (used for Wo)
__global__ void __launch_bounds__(256)
gemm_tc_kernel(const float* __restrict__ A, const float* __restrict__ W,
               float* __restrict__ C, int M, int Nc, int K) {
    gemm_tc_body(A, W, C, M, Nc, K);
}

// merged Q/K/V projections: grid.z selects which GEMM
__global__ void __launch_bounds__(256)
gemm_qkv_kernel(const float* q_in, const float* k_in, const float* v_in,
                const float* Wq, const float* Wk, const float* Wv,
                float* qb, float* kb, float* vb) {
    int z = blockIdx.z;
    const float* A = (z == 0) ? q_in : (z == 1) ? k_in : v_in;
    const float* W = (z == 0) ? Wq : (z == 1) ? Wk : Wv;
    float* C = (z == 0) ? qb : (z == 1) ? kb : vb;
    gemm_tc_body(A, W, C, MTOT, HID, HID);
}

// ---------------- Flash attention (tensor core, tf32) ------------------------
// grid (T/128, 32, B), block 256 (8 warps x 16 rows). NO occupancy pin (R5 codegen).
// dynamic smem: Qs[128][36] | Ks[64][36] | Vs[64][72] | Ps[128][72]
#define QKPAD 36
#define FL_SMEM_WORDS (128*QKPAD + 64*QKPAD + 64*72 + 128*72)
__global__ void __launch_bounds__(256)
flash_tc_kernel() {
    extern __shared__ u32 sm[];
    u32 (*Qs)[QKPAD] = (u32(*)[QKPAD])(sm);
    u32 (*Ks)[QKPAD] = (u32(*)[QKPAD])(sm + 128 * QKPAD);
    u32 (*Vs)[72]    = (u32(*)[72])(sm + 128 * QKPAD + 64 * QKPAD);
    u32 (*Ps)[72]    = (u32(*)[72])(sm + 128 * QKPAD + 64 * QKPAD + 64 * 72);

    int tid = threadIdx.x;
    int warp = tid >> 5;
    int lane = tid & 31;
    int g = lane >> 2, t = lane & 3;
    int wm = warp * 16;
    int qt0 = blockIdx.x * 128;
    int hh = blockIdx.y;
    int b = blockIdx.z;

    const float* qb = g_qb;
    const float* kb = g_kb;
    const float* vb = g_vb;

    // load Q tile (128 x 32)
    #pragma unroll
    for (int it = 0; it < 4; it++) {
        int idx = tid + it * 256;
        int m = idx >> 3;
        int kq = (idx & 7) * 4;
        float4 v = *(const float4*)&qb[((size_t)(b * TT) + qt0 + m) * HID + hh * 32 + kq];
        Qs[m][kq + 0] = f2tf(v.x); Qs[m][kq + 1] = f2tf(v.y);
        Qs[m][kq + 2] = f2tf(v.z); Qs[m][kq + 3] = f2tf(v.w);
    }

    float oacc[8][4];
    #pragma unroll
    for (int dt = 0; dt < 8; dt++)
        #pragma unroll
        for (int i = 0; i < 4; i++) oacc[dt][i] = 0.f;
    float m0s = -1e30f, m1s = -1e30f, l0 = 0.f, l1 = 0.f;

    for (int nt0 = 0; nt0 < qt0 + 128; nt0 += 64) {
        __syncthreads();   // protect Ks/Vs from previous iteration's readers
        // load K tile (64 x 32)
        #pragma unroll
        for (int it = 0; it < 2; it++) {
            int idx = tid + it * 256;
            int n = idx >> 3;
            int kq = (idx & 7) * 4;
            float4 v = *(const float4*)&kb[((size_t)(b * NN) + nt0 + n) * HID + hh * 32 + kq];
            Ks[n][kq + 0] = f2tf(v.x); Ks[n][kq + 1] = f2tf(v.y);
            Ks[n][kq + 2] = f2tf(v.z); Ks[n][kq + 3] = f2tf(v.w);
        }
        // load V tile (64 x 64)
        #pragma unroll
        for (int it = 0; it < 4; it++) {
            int idx = tid + it * 256;
            int n = idx >> 4;
            int dq = (idx & 15) * 4;
            float4 v = *(const float4*)&vb[((size_t)(b * NN) + nt0 + n) * HID + (hh >> 1) * 64 + dq];
            Vs[n][dq + 0] = f2tf(v.x); Vs[n][dq + 1] = f2tf(v.y);
            Vs[n][dq + 2] = f2tf(v.z); Vs[n][dq + 3] = f2tf(v.w);
        }
        __syncthreads();

        // S = Q K^T  (warp: 16 rows x 64 cols = 8 n-tiles)
        float s[8][4];
        #pragma unroll
        for (int nt = 0; nt < 8; nt++)
            #pragma unroll
            for (int i = 0; i < 4; i++) s[nt][i] = 0.f;

        #pragma unroll
        for (int ks = 0; ks < 32; ks += 8) {
            u32 qa0 = Qs[wm + g][ks + t];
            u32 qa1 = Qs[wm + g + 8][ks + t];
            u32 qa2 = Qs[wm + g][ks + t + 4];
            u32 qa3 = Qs[wm + g + 8][ks + t + 4];
            #pragma unroll
            for (int nt = 0; nt < 8; nt++) {
                u32 kb0 = Ks[nt * 8 + g][ks + t];
                u32 kb1 = Ks[nt * 8 + g][ks + t + 4];
                mma_tf32(s[nt], qa0, qa1, qa2, qa3, kb0, kb1);
            }
        }

        // scale + causal mask
        int row0 = qt0 + wm + g;
        int row1 = row0 + 8;
        #pragma unroll
        for (int nt = 0; nt < 8; nt++) {
            int c0 = nt0 + nt * 8 + 2 * t;
            int c1 = c0 + 1;
            s[nt][0] = (c0 <= row0) ? s[nt][0] * SCALE : -1e30f;
            s[nt][1] = (c1 <= row0) ? s[nt][1] * SCALE : -1e30f;
            s[nt][2] = (c0 <= row1) ? s[nt][2] * SCALE : -1e30f;
            s[nt][3] = (c1 <= row1) ? s[nt][3] * SCALE : -1e30f;
        }

        // online softmax (row0 -> regs 0,1 ; row1 -> regs 2,3)
        float rm0 = -1e30f, rm1 = -1e30f;
        #pragma unroll
        for (int nt = 0; nt < 8; nt++) {
            rm0 = fmaxf(rm0, fmaxf(s[nt][0], s[nt][1]));
            rm1 = fmaxf(rm1, fmaxf(s[nt][2], s[nt][3]));
        }
        #pragma unroll
        for (int off = 1; off < 4; off <<= 1) {
            rm0 = fmaxf(rm0, __shfl_xor_sync(0xffffffffu, rm0, off));
            rm1 = fmaxf(rm1, __shfl_xor_sync(0xffffffffu, rm1, off));
        }
        float mn0 = fmaxf(m0s, rm0), mn1 = fmaxf(m1s, rm1);
        float al0 = __expf(m0s - mn0), al1 = __expf(m1s - mn1);
        float rs0 = 0.f, rs1 = 0.f;
        #pragma unroll
        for (int nt = 0; nt < 8; nt++) {
            s[nt][0] = __expf(s[nt][0] - mn0);
            s[nt][1] = __expf(s[nt][1] - mn0);
            s[nt][2] = __expf(s[nt][2] - mn1);
            s[nt][3] = __expf(s[nt][3] - mn1);
            rs0 += s[nt][0] + s[nt][1];
            rs1 += s[nt][2] + s[nt][3];
        }
        #pragma unroll
        for (int off = 1; off < 4; off <<= 1) {
            rs0 += __shfl_xor_sync(0xffffffffu, rs0, off);
            rs1 += __shfl_xor_sync(0xffffffffu, rs1, off);
        }
        l0 = l0 * al0 + rs0;
        l1 = l1 * al1 + rs1;
        m0s = mn0; m1s = mn1;
        #pragma unroll
        for (int dt = 0; dt < 8; dt++) {
            oacc[dt][0] *= al0; oacc[dt][1] *= al0;
            oacc[dt][2] *= al1; oacc[dt][3] *= al1;
        }

        // store P fragments to smem (warp-private rows)
        #pragma unroll
        for (int nt = 0; nt < 8; nt++) {
            Ps[wm + g][nt * 8 + 2 * t]         = f2tf(s[nt][0]);
            Ps[wm + g][nt * 8 + 2 * t + 1]     = f2tf(s[nt][1]);
            Ps[wm + g + 8][nt * 8 + 2 * t]     = f2tf(s[nt][2]);
            Ps[wm + g + 8][nt * 8 + 2 * t + 1] = f2tf(s[nt][3]);
        }
        __syncwarp();

        // O += P V : k = 64 local cols, 8 k-steps; dv = 64, 8 tiles
        #pragma unroll
        for (int kk = 0; kk < 8; kk++) {
            u32 pa0 = Ps[wm + g][kk * 8 + t];
            u32 pa1 = Ps[wm + g + 8][kk * 8 + t];
            u32 pa2 = Ps[wm + g][kk * 8 + t + 4];
            u32 pa3 = Ps[wm + g + 8][kk * 8 + t + 4];
            #pragma unroll
            for (int dt = 0; dt < 8; dt++) {
                u32 vb0 = Vs[kk * 8 + t][dt * 8 + g];
                u32 vb1 = Vs[kk * 8 + t + 4][dt * 8 + g];
                mma_tf32(oacc[dt], pa0, pa1, pa2, pa3, vb0, vb1);
            }
        }
        __syncwarp();
    }

    // epilogue
    float inv0 = 1.0f / l0, inv1 = 1.0f / l1;
    int trow = qt0 + wm + g;
    size_t base = (((size_t)b * NHH + hh) * TT);
    #pragma unroll
    for (int dt = 0; dt < 8; dt++) {
        int col = dt * 8 + 2 * t;
        *(float2*)&g_ob[(base + trow) * DH + col] =
            make_float2(oacc[dt][0] * inv0, oacc[dt][1] * inv0);
        *(float2*)&g_ob[(base + trow + 8) * DH + col] =
            make_float2(oacc[dt][2] * inv1, oacc[dt][3] * inv1);
    }
}

// ---------------- combine -----------------------------------------------------
__global__ void __launch_bounds__(256)
combine_kernel(const float* __restrict__ g) {
    int gwarp = (blockIdx.x * blockDim.x + threadIdx.x) >> 5;
    int lane = threadIdx.x & 31;
    if (gwarp >= BB * HH * TT) return;
    int t = gwarp % TT;
    int h = (gwarp / TT) % HH;
    int b = gwarp / (HH * TT);

    float lam = g_lambda;
    const float* o1 = g_ob + (((size_t)b * NHH + 2 * h) * TT + t) * DH;
    const float* o2 = g_ob + (((size_t)b * NHH + 2 * h + 1) * TT + t) * DH;

    float x0 = o1[lane]      - lam * o2[lane];
    float x1 = o1[lane + 32] - lam * o2[lane + 32];

    float ss = x0 * x0 + x1 * x1;
    #pragma unroll
    for (int off = 16; off > 0; off >>= 1)
        ss += __shfl_xor_sync(0xffffffffu, ss, off);

    float inv = rsqrtf(ss * (1.0f / DH) + EPSV);
    float sc = (1.0f - LAMBDA_INIT) * inv;

    float* xb = g_xb + ((size_t)b * TT + t) * HID + h * DH;
    xb[lane]      = x0 * sc * g[lane];
    xb[lane + 32] = x1 * sc * g[lane + 32];
}

// ---------------- launch ------------------------------------------------------
extern "C" void kernel_launch(void* const* d_in, const int* in_sizes, int n_in,
                              void* d_out, int out_size) {
    const float* query = (const float*)d_in[0];
    const float* key_  = (const float*)d_in[1];
    const float* value = (const float*)d_in[2];
    const float* Wq    = (const float*)d_in[3];
    const float* Wk    = (const float*)d_in[4];
    const float* Wv    = (const float*)d_in[5];
    const float* Wo    = (const float*)d_in[6];
    const float* lq1   = (const float*)d_in[7];
    const float* lq2   = (const float*)d_in[8];
    const float* lk1   = (const float*)d_in[9];
    const float* lk2   = (const float*)d_in[10];
    const float* gw    = (const float*)d_in[11];
    float* out = (float*)d_out;

    float *qb, *kb, *vb, *xb;
    cudaGetSymbolAddress((void**)&qb, g_qb);
    cudaGetSymbolAddress((void**)&kb, g_kb);
    cudaGetSymbolAddress((void**)&vb, g_vb);
    cudaGetSymbolAddress((void**)&xb, g_xb);

    cudaFuncSetAttribute(flash_tc_kernel,
                         cudaFuncAttributeMaxDynamicSharedMemorySize,
                         FL_SMEM_WORDS * 4);

    lambda_kernel<<<1, 32>>>(lq1, lq2, lk1, lk2);

    // merged Q/K/V projections
    gemm_qkv_kernel<<<dim3(HID / 128, MTOT / 128, 3), 256>>>(
        query, key_, value, Wq, Wk, Wv, qb, kb, vb);

    flash_tc_kernel<<<dim3(TT / 128, NHH, BB), 256, FL_SMEM_WORDS * 4>>>();

    int nwarps = BB * HH * TT;
    combine_kernel<<<(nwarps * 32 + 255) / 256, 256>>>(gw);

    gemm_tc_kernel<<<dim3(HID / 128, MTOT / 128), 256>>>(xb, Wo, out, MTOT, HID, HID);
}

// round 10
// speedup vs baseline: 1.0791x; 1.0791x over previous
#include <cuda_runtime.h>
#include <cuda_bf16.h>
#include <cstdint>
#include <math.h>

typedef unsigned int u32;

// Problem constants
#define BB 2
#define TT 2048
#define NN 2048
#define HID 1024
#define HH 16
#define DH 64
#define HALF 32
#define NHH 32
#define MTOT (BB*TT)

#define LAMBDA_INIT 0.7008206631f
#define EPSV 1e-5f
#define SCALE 0.17677669529663689f  // 1/sqrt(32)

// ---------------- scratch ----------------------------------------------------
__device__ float g_qb[MTOT * HID];
__device__ float g_kb[BB * NN * HID];
__device__ float g_vb[BB * NN * HID];
__device__ float g_ob[BB * NHH * TT * DH];
__device__ float g_xb[MTOT * HID];
__device__ float g_lambda;

// ---------------- helpers ----------------------------------------------------
__device__ __forceinline__ u32 f2tf(float f) {
    u32 u;
    asm("cvt.rna.tf32.f32 %0, %1;" : "=r"(u) : "f"(f));
    return u;
}

__device__ __forceinline__ void mma_tf32(float c[4],
                                         u32 a0, u32 a1, u32 a2, u32 a3,
                                         u32 b0, u32 b1) {
    asm volatile(
        "mma.sync.aligned.m16n8k8.row.col.f32.tf32.tf32.f32 "
        "{%0,%1,%2,%3},{%4,%5,%6,%7},{%8,%9},{%0,%1,%2,%3};\n"
        : "+f"(c[0]), "+f"(c[1]), "+f"(c[2]), "+f"(c[3])
        : "r"(a0), "r"(a1), "r"(a2), "r"(a3), "r"(b0), "r"(b1));
}

// ---------------- lambda ------------------------------------------------------
__global__ void lambda_kernel(const float* __restrict__ lq1, const float* __restrict__ lq2,
                              const float* __restrict__ lk1, const float* __restrict__ lk2) {
    int lane = threadIdx.x;
    float a = lq1[lane] * lk1[lane];
    float b = lq2[lane] * lk2[lane];
    #pragma unroll
    for (int off = 16; off > 0; off >>= 1) {
        a += __shfl_xor_sync(0xffffffffu, a, off);
        b += __shfl_xor_sync(0xffffffffu, b, off);
    }
    if (lane == 0) g_lambda = expf(a) - expf(b) + LAMBDA_INIT;
}

// ---------------- GEMM (tensor core, tf32): C = A @ W^T ----------------------
// 128x128 tile, BK=16 double-buffered, 256 threads (8 warps: 4 M x 2 N, 32x64 each).
// R5 layout: [m][k] rows, consecutive-word staging stores (STS.128-mergeable).
#define GPAD 20

__device__ __forceinline__ void gemm_tc_body(const float* __restrict__ A,
                                             const float* __restrict__ W,
                                             float* __restrict__ C,
                                             int M, int Nc, int K) {
    __shared__ u32 As[2][128][GPAD];
    __shared__ u32 Ws[2][128][GPAD];

    int tid = threadIdx.x;
    int warp = tid >> 5;
    int lane = tid & 31;
    int g = lane >> 2, t = lane & 3;
    int wy = warp >> 1;          // 0..3 (M)
    int wx = warp & 1;           // 0..1 (N)
    int m0 = blockIdx.y * 128;
    int n0 = blockIdx.x * 128;

    int lm = tid >> 2;           // row within 64-row chunk
    int lk = (tid & 3) * 4;      // k offset (0,4,8,12)

    float acc[2][8][4];
    #pragma unroll
    for (int mt = 0; mt < 2; mt++)
        #pragma unroll
        for (int nt = 0; nt < 8; nt++)
            #pragma unroll
            for (int i = 0; i < 4; i++) acc[mt][nt][i] = 0.f;

    // initial tile load (k0 = 0)
    #pragma unroll
    for (int it = 0; it < 2; it++) {
        int m = lm + it * 64;
        float4 av = *(const float4*)&A[(size_t)(m0 + m) * K + lk];
        float4 wv = *(const float4*)&W[(size_t)(n0 + m) * K + lk];
        As[0][m][lk + 0] = f2tf(av.x); As[0][m][lk + 1] = f2tf(av.y);
        As[0][m][lk + 2] = f2tf(av.z); As[0][m][lk + 3] = f2tf(av.w);
        Ws[0][m][lk + 0] = f2tf(wv.x); Ws[0][m][lk + 1] = f2tf(wv.y);
        Ws[0][m][lk + 2] = f2tf(wv.z); Ws[0][m][lk + 3] = f2tf(wv.w);
    }
    __syncthreads();

    int nk = K / 16;
    for (int kt = 0; kt < nk; kt++) {
        int buf = kt & 1;
        float4 av[2], wv[2];
        if (kt + 1 < nk) {
            int k0 = (kt + 1) * 16;
            #pragma unroll
            for (int it = 0; it < 2; it++) {
                int m = lm + it * 64;
                av[it] = *(const float4*)&A[(size_t)(m0 + m) * K + k0 + lk];
                wv[it] = *(const float4*)&W[(size_t)(n0 + m) * K + k0 + lk];
            }
        }

        #pragma unroll
        for (int ks = 0; ks < 16; ks += 8) {
            u32 afr[2][4];
            #pragma unroll
            for (int mt = 0; mt < 2; mt++) {
                int mr = wy * 32 + mt * 16;
                afr[mt][0] = As[buf][mr + g][ks + t];
                afr[mt][1] = As[buf][mr + g + 8][ks + t];
                afr[mt][2] = As[buf][mr + g][ks + t + 4];
                afr[mt][3] = As[buf][mr + g + 8][ks + t + 4];
            }
            u32 bfr[8][2];
            #pragma unroll
            for (int nt = 0; nt < 8; nt++) {
                int nr = wx * 64 + nt * 8 + g;
                bfr[nt][0] = Ws[buf][nr][ks + t];
                bfr[nt][1] = Ws[buf][nr][ks + t + 4];
            }
            #pragma unroll
            for (int mt = 0; mt < 2; mt++)
                #pragma unroll
                for (int nt = 0; nt < 8; nt++)
                    mma_tf32(acc[mt][nt], afr[mt][0], afr[mt][1], afr[mt][2], afr[mt][3],
                             bfr[nt][0], bfr[nt][1]);
        }

        if (kt + 1 < nk) {
            int nb = buf ^ 1;
            #pragma unroll
            for (int it = 0; it < 2; it++) {
                int m = lm + it * 64;
                As[nb][m][lk + 0] = f2tf(av[it].x); As[nb][m][lk + 1] = f2tf(av[it].y);
                As[nb][m][lk + 2] = f2tf(av[it].z); As[nb][m][lk + 3] = f2tf(av[it].w);
                Ws[nb][m][lk + 0] = f2tf(wv[it].x); Ws[nb][m][lk + 1] = f2tf(wv[it].y);
                Ws[nb][m][lk + 2] = f2tf(wv[it].z); Ws[nb][m][lk + 3] = f2tf(wv[it].w);
            }
        }
        __syncthreads();
    }

    // epilogue
    #pragma unroll
    for (int mt = 0; mt < 2; mt++) {
        #pragma unroll
        for (int nt = 0; nt < 8; nt++) {
            int row = m0 + wy * 32 + mt * 16 + g;
            int col = n0 + wx * 64 + nt * 8 + 2 * t;
            *(float2*)&C[(size_t)row * Nc + col] = make_float2(acc[mt][nt][0], acc[mt][nt][1]);
            *(float2*)&C[(size_t)(row + 8) * Nc + col] = make_float2(acc[mt][nt][2], acc[mt][nt][3]);
        }
    }
}

// single GEMM (used for Wo)
__global__ void __launch_bounds__(256)
gemm_tc_kernel(const float* __restrict__ A, const float* __restrict__ W,
               float* __restrict__ C, int M, int Nc, int K) {
    gemm_tc_body(A, W, C, M, Nc, K);
}

// merged Q/K/V projections: grid.z selects which GEMM
__global__ void __launch_bounds__(256)
gemm_qkv_kernel(const float* q_in, const float* k_in, const float* v_in,
                const float* Wq, const float* Wk, const float* Wv,
                float* qb, float* kb, float* vb) {
    int z = blockIdx.z;
    const float* A = (z == 0) ? q_in : (z == 1) ? k_in : v_in;
    const float* W = (z == 0) ? Wq : (z == 1) ? Wk : Wv;
    float* C = (z == 0) ? qb : (z == 1) ? kb : vb;
    gemm_tc_body(A, W, C, MTOT, HID, HID);
}

// ---------------- Flash attention (tensor core, tf32) ------------------------
// grid (T/128, 32, B), block 256 (8 warps x 16 rows). R5 codegen (no occupancy pin).
// dynamic smem: Qs[128][36] | Ks[64][36] | Vs[64][72] | Ps[128][72]
#define QKPAD 36
#define FL_SMEM_WORDS (128*QKPAD + 64*QKPAD + 64*72 + 128*72)
__global__ void __launch_bounds__(256)
flash_tc_kernel() {
    extern __shared__ u32 sm[];
    u32 (*Qs)[QKPAD] = (u32(*)[QKPAD])(sm);
    u32 (*Ks)[QKPAD] = (u32(*)[QKPAD])(sm + 128 * QKPAD);
    u32 (*Vs)[72]    = (u32(*)[72])(sm + 128 * QKPAD + 64 * QKPAD);
    u32 (*Ps)[72]    = (u32(*)[72])(sm + 128 * QKPAD + 64 * QKPAD + 64 * 72);

    int tid = threadIdx.x;
    int warp = tid >> 5;
    int lane = tid & 31;
    int g = lane >> 2, t = lane & 3;
    int wm = warp * 16;
    int qt0 = blockIdx.x * 128;
    int hh = blockIdx.y;
    int b = blockIdx.z;

    const float* qb = g_qb;
    const float* kb = g_kb;
    const float* vb = g_vb;

    // load Q tile (128 x 32)
    #pragma unroll
    for (int it = 0; it < 4; it++) {
        int idx = tid + it * 256;
        int m = idx >> 3;
        int kq = (idx & 7) * 4;
        float4 v = *(const float4*)&qb[((size_t)(b * TT) + qt0 + m) * HID + hh * 32 + kq];
        Qs[m][kq + 0] = f2tf(v.x); Qs[m][kq + 1] = f2tf(v.y);
        Qs[m][kq + 2] = f2tf(v.z); Qs[m][kq + 3] = f2tf(v.w);
    }

    float oacc[8][4];
    #pragma unroll
    for (int dt = 0; dt < 8; dt++)
        #pragma unroll
        for (int i = 0; i < 4; i++) oacc[dt][i] = 0.f;
    float m0s = -1e30f, m1s = -1e30f, l0 = 0.f, l1 = 0.f;

    for (int nt0 = 0; nt0 < qt0 + 128; nt0 += 64) {
        __syncthreads();   // protect Ks/Vs from previous iteration's readers
        // load K tile (64 x 32)
        #pragma unroll
        for (int it = 0; it < 2; it++) {
            int idx = tid + it * 256;
            int n = idx >> 3;
            int kq = (idx & 7) * 4;
            float4 v = *(const float4*)&kb[((size_t)(b * NN) + nt0 + n) * HID + hh * 32 + kq];
            Ks[n][kq + 0] = f2tf(v.x); Ks[n][kq + 1] = f2tf(v.y);
            Ks[n][kq + 2] = f2tf(v.z); Ks[n][kq + 3] = f2tf(v.w);
        }
        // load V tile (64 x 64)
        #pragma unroll
        for (int it = 0; it < 4; it++) {
            int idx = tid + it * 256;
            int n = idx >> 4;
            int dq = (idx & 15) * 4;
            float4 v = *(const float4*)&vb[((size_t)(b * NN) + nt0 + n) * HID + (hh >> 1) * 64 + dq];
            Vs[n][dq + 0] = f2tf(v.x); Vs[n][dq + 1] = f2tf(v.y);
            Vs[n][dq + 2] = f2tf(v.z); Vs[n][dq + 3] = f2tf(v.w);
        }
        __syncthreads();

        // S = Q K^T  (warp: 16 rows x 64 cols = 8 n-tiles)
        float s[8][4];
        #pragma unroll
        for (int nt = 0; nt < 8; nt++)
            #pragma unroll
            for (int i = 0; i < 4; i++) s[nt][i] = 0.f;

        #pragma unroll
        for (int ks = 0; ks < 32; ks += 8) {
            u32 qa0 = Qs[wm + g][ks + t];
            u32 qa1 = Qs[wm + g + 8][ks + t];
            u32 qa2 = Qs[wm + g][ks + t + 4];
            u32 qa3 = Qs[wm + g + 8][ks + t + 4];
            #pragma unroll
            for (int nt = 0; nt < 8; nt++) {
                u32 kb0 = Ks[nt * 8 + g][ks + t];
                u32 kb1 = Ks[nt * 8 + g][ks + t + 4];
                mma_tf32(s[nt], qa0, qa1, qa2, qa3, kb0, kb1);
            }
        }

        // scale + causal mask
        int row0 = qt0 + wm + g;
        int row1 = row0 + 8;
        #pragma unroll
        for (int nt = 0; nt < 8; nt++) {
            int c0 = nt0 + nt * 8 + 2 * t;
            int c1 = c0 + 1;
            s[nt][0] = (c0 <= row0) ? s[nt][0] * SCALE : -1e30f;
            s[nt][1] = (c1 <= row0) ? s[nt][1] * SCALE : -1e30f;
            s[nt][2] = (c0 <= row1) ? s[nt][2] * SCALE : -1e30f;
            s[nt][3] = (c1 <= row1) ? s[nt][3] * SCALE : -1e30f;
        }

        // online softmax (row0 -> regs 0,1 ; row1 -> regs 2,3)
        float rm0 = -1e30f, rm1 = -1e30f;
        #pragma unroll
        for (int nt = 0; nt < 8; nt++) {
            rm0 = fmaxf(rm0, fmaxf(s[nt][0], s[nt][1]));
            rm1 = fmaxf(rm1, fmaxf(s[nt][2], s[nt][3]));
        }
        #pragma unroll
        for (int off = 1; off < 4; off <<= 1) {
            rm0 = fmaxf(rm0, __shfl_xor_sync(0xffffffffu, rm0, off));
            rm1 = fmaxf(rm1, __shfl_xor_sync(0xffffffffu, rm1, off));
        }
        float mn0 = fmaxf(m0s, rm0), mn1 = fmaxf(m1s, rm1);
        float al0 = __expf(m0s - mn0), al1 = __expf(m1s - mn1);
        float rs0 = 0.f, rs1 = 0.f;
        #pragma unroll
        for (int nt = 0; nt < 8; nt++) {
            s[nt][0] = __expf(s[nt][0] - mn0);
            s[nt][1] = __expf(s[nt][1] - mn0);
            s[nt][2] = __expf(s[nt][2] - mn1);
            s[nt][3] = __expf(s[nt][3] - mn1);
            rs0 += s[nt][0] + s[nt][1];
            rs1 += s[nt][2] + s[nt][3];
        }
        #pragma unroll
        for (int off = 1; off < 4; off <<= 1) {
            rs0 += __shfl_xor_sync(0xffffffffu, rs0, off);
            rs1 += __shfl_xor_sync(0xffffffffu, rs1, off);
        }
        l0 = l0 * al0 + rs0;
        l1 = l1 * al1 + rs1;
        m0s = mn0; m1s = mn1;
        #pragma unroll
        for (int dt = 0; dt < 8; dt++) {
            oacc[dt][0] *= al0; oacc[dt][1] *= al0;
            oacc[dt][2] *= al1; oacc[dt][3] *= al1;
        }

        // store P fragments to smem (warp-private rows)
        #pragma unroll
        for (int nt = 0; nt < 8; nt++) {
            Ps[wm + g][nt * 8 + 2 * t]         = f2tf(s[nt][0]);
            Ps[wm + g][nt * 8 + 2 * t + 1]     = f2tf(s[nt][1]);
            Ps[wm + g + 8][nt * 8 + 2 * t]     = f2tf(s[nt][2]);
            Ps[wm + g + 8][nt * 8 + 2 * t + 1] = f2tf(s[nt][3]);
        }
        __syncwarp();

        // O += P V : k = 64 local cols, 8 k-steps; dv = 64, 8 tiles
        #pragma unroll
        for (int kk = 0; kk < 8; kk++) {
            u32 pa0 = Ps[wm + g][kk * 8 + t];
            u32 pa1 = Ps[wm + g + 8][kk * 8 + t];
            u32 pa2 = Ps[wm + g][kk * 8 + t + 4];
            u32 pa3 = Ps[wm + g + 8][kk * 8 + t + 4];
            #pragma unroll
            for (int dt = 0; dt < 8; dt++) {
                u32 vb0 = Vs[kk * 8 + t][dt * 8 + g];
                u32 vb1 = Vs[kk * 8 + t + 4][dt * 8 + g];
                mma_tf32(oacc[dt], pa0, pa1, pa2, pa3, vb0, vb1);
            }
        }
        __syncwarp();
    }

    // epilogue
    float inv0 = 1.0f / l0, inv1 = 1.0f / l1;
    int trow = qt0 + wm + g;
    size_t base = (((size_t)b * NHH + hh) * TT);
    #pragma unroll
    for (int dt = 0; dt < 8; dt++) {
        int col = dt * 8 + 2 * t;
        *(float2*)&g_ob[(base + trow) * DH + col] =
            make_float2(oacc[dt][0] * inv0, oacc[dt][1] * inv0);
        *(float2*)&g_ob[(base + trow + 8) * DH + col] =
            make_float2(oacc[dt][2] * inv1, oacc[dt][3] * inv1);
    }
}

// ---------------- combine -----------------------------------------------------
__global__ void __launch_bounds__(256)
combine_kernel(const float* __restrict__ g) {
    int gwarp = (blockIdx.x * blockDim.x + threadIdx.x) >> 5;
    int lane = threadIdx.x & 31;
    if (gwarp >= BB * HH * TT) return;
    int t = gwarp % TT;
    int h = (gwarp / TT) % HH;
    int b = gwarp / (HH * TT);

    float lam = g_lambda;
    const float* o1 = g_ob + (((size_t)b * NHH + 2 * h) * TT + t) * DH;
    const float* o2 = g_ob + (((size_t)b * NHH + 2 * h + 1) * TT + t) * DH;

    float x0 = o1[lane]      - lam * o2[lane];
    float x1 = o1[lane + 32] - lam * o2[lane + 32];

    float ss = x0 * x0 + x1 * x1;
    #pragma unroll
    for (int off = 16; off > 0; off >>= 1)
        ss += __shfl_xor_sync(0xffffffffu, ss, off);

    float inv = rsqrtf(ss * (1.0f / DH) + EPSV);
    float sc = (1.0f - LAMBDA_INIT) * inv;

    float* xb = g_xb + ((size_t)b * TT + t) * HID + h * DH;
    xb[lane]      = x0 * sc * g[lane];
    xb[lane + 32] = x1 * sc * g[lane + 32];
}

// ---------------- launch ------------------------------------------------------
extern "C" void kernel_launch(void* const* d_in, const int* in_sizes, int n_in,
                              void* d_out, int out_size) {
    const float* query = (const float*)d_in[0];
    const float* key_  = (const float*)d_in[1];
    const float* value = (const float*)d_in[2];
    const float* Wq    = (const float*)d_in[3];
    const float* Wk    = (const float*)d_in[4];
    const float* Wv    = (const float*)d_in[5];
    const float* Wo    = (const float*)d_in[6];
    const float* lq1   = (const float*)d_in[7];
    const float* lq2   = (const float*)d_in[8];
    const float* lk1   = (const float*)d_in[9];
    const float* lk2   = (const float*)d_in[10];
    const float* gw    = (const float*)d_in[11];
    float* out = (float*)d_out;

    float *qb, *kb, *vb, *xb;
    cudaGetSymbolAddress((void**)&qb, g_qb);
    cudaGetSymbolAddress((void**)&kb, g_kb);
    cudaGetSymbolAddress((void**)&vb, g_vb);
    cudaGetSymbolAddress((void**)&xb, g_xb);

    cudaFuncSetAttribute(flash_tc_kernel,
                         cudaFuncAttributeMaxDynamicSharedMemorySize,
                         FL_SMEM_WORDS * 4);

    lambda_kernel<<<1, 32>>>(lq1, lq2, lk1, lk2);

    // merged Q/K/V projections
    gemm_qkv_kernel<<<dim3(HID / 128, MTOT / 128, 3), 256>>>(
        query, key_, value, Wq, Wk, Wv, qb, kb, vb);

    flash_tc_kernel<<<dim3(TT / 128, NHH, BB), 256, FL_SMEM_WORDS * 4>>>();

    int nwarps = BB * HH * TT;
    combine_kernel<<<(nwarps * 32 + 255) / 256, 256>>>(gw);

    gemm_tc_kernel<<<dim3(HID / 128, MTOT / 128), 256>>>(xb, Wo, out, MTOT, HID, HID);
}